// round 10
// baseline (speedup 1.0000x reference)
#include <cuda_runtime.h>
#include <cub/cub.cuh>
#include <cstdint>

// ---------------- problem constants ----------------
#define NPTS     3145728
#define GDIM     128
#define NUM_VOX  2097152   // GDIM^3
#define KCAP     16
#define DDESC    24

// output layout (floats), tuple order of the reference
#define OFF_PTS   ((size_t)0)
#define OFF_CONF  ((size_t)3 * NPTS)
#define OFF_DESC  ((size_t)4 * NPTS)
#define OFF_DC    ((size_t)28 * NPTS)
#define OFF_GRID  ((size_t)29 * NPTS)
#define OFF_VC    (OFF_GRID + (size_t)NUM_VOX * KCAP)

// ---------------- device scratch (static: no allocation allowed) ----------------
__device__ unsigned g_sconf[NPTS];                    // conf bits, ascending-sorted
__device__ unsigned g_vid[NPTS];
__device__ unsigned g_pid[NPTS];                      // compact slot -> point id
__device__ float4   g_rec[(size_t)2 * NPTS];          // 32B/point: {x,y,z,conf},{dc,-,-,-}
__device__ unsigned long long g_bins[NPTS];           // per-voxel (~conf,idx) keys
__device__ unsigned g_counts[NUM_VOX + 1];
__device__ unsigned long long g_cvals64[NUM_VOX + 1]; // (capped<<32)|count
__device__ unsigned long long g_scan64[NUM_VOX + 1];  // (coffs <<32)|offsets
__device__ unsigned char g_temp[(size_t)64 * 1024 * 1024];   // sort temp
__device__ unsigned char g_temp2[(size_t)16 * 1024 * 1024];  // scan temp

// ---------------- kernels ----------------

// voxel id + histogram
__global__ void k_prep(const float* __restrict__ pts,
                       const float* __restrict__ center) {
    int i = blockIdx.x * blockDim.x + threadIdx.x;
    if (i >= NPTS) return;

    const float HALF = (float)((256.0 * 0.02) / 2.0);   // CUBE/2
    // XLA rewrites divide-by-constant into multiply by reciprocal;
    // f32(1 / f32(0.04)) rounds to exactly 25.0f.
    const float INV_MRES = 25.0f;

    float mx = center[0] - HALF;
    float my = center[1] - HALF;
    float mz = center[2] - HALF;

    float px = pts[3 * (size_t)i + 0];
    float py = pts[3 * (size_t)i + 1];
    float pz = pts[3 * (size_t)i + 2];

    int ix = (int)((px - mx) * INV_MRES);
    int iy = (int)((py - my) * INV_MRES);
    int iz = (int)((pz - mz) * INV_MRES);

    bool inb = (ix >= 0) && (ix < GDIM) && (iy >= 0) && (iy < GDIM) &&
               (iz >= 0) && (iz < GDIM);
    unsigned v = inb ? (unsigned)(ix * GDIM * GDIM + iy * GDIM + iz)
                     : (unsigned)NUM_VOX;
    g_vid[i] = v;
    atomicAdd(&g_counts[v], 1u);
}

// packed counts for the fused dual scan
__global__ void k_capped() {
    int v = blockIdx.x * blockDim.x + threadIdx.x;
    if (v > NUM_VOX) return;
    unsigned c = g_counts[v];
    unsigned capped = (v < NUM_VOX) ? min(c, (unsigned)KCAP) : 0u;
    g_cvals64[v] = ((unsigned long long)capped << 32) | (unsigned long long)c;
}

// binning + staging-record build. All reads coalesced; unique bin slots via
// atomicSub on the (now dead) counts array.
__global__ void k_bin(const float* __restrict__ pts,
                      const float* __restrict__ conf,
                      const float* __restrict__ dconf,
                      const float* __restrict__ dcm,
                      const float* __restrict__ dcs) {
    int i = blockIdx.x * blockDim.x + threadIdx.x;
    if (i >= NPTS) return;

    // staging record: 1 random 32B sector in k_out replaces 4 random sectors
    float4 r0;
    r0.x = pts[3 * (size_t)i + 0];
    r0.y = pts[3 * (size_t)i + 1];
    r0.z = pts[3 * (size_t)i + 2];
    // faithful quirk value: conf_sorted(desc)[p] == asc-sorted[N-1-p]
    r0.w = __uint_as_float(g_sconf[NPTS - 1 - i]);
    float dc = __fdiv_rn(dconf[i] - dcm[0], dcs[0]);
    g_rec[2 * (size_t)i]     = r0;
    g_rec[2 * (size_t)i + 1] = make_float4(dc, 0.f, 0.f, 0.f);

    unsigned v = g_vid[i];
    if (v >= NUM_VOX) return;
    unsigned slot = atomicSub(&g_counts[v], 1u) - 1u;
    unsigned off = (unsigned)g_scan64[v];           // offsets[v]
    unsigned long long key =
        ((unsigned long long)(~__float_as_uint(conf[i])) << 32) |
        (unsigned long long)(unsigned)i;
    g_bins[off + slot] = key;
}

// per-voxel top-16 selection -> compact pid list + analytic grid/vox_counts
__global__ void k_rank_grid(float* __restrict__ out) {
    int v = blockIdx.x * blockDim.x + threadIdx.x;
    if (v >= NUM_VOX) return;
    unsigned long long s0 = g_scan64[v];
    unsigned long long s1 = g_scan64[v + 1];
    unsigned off  = (unsigned)s0;
    unsigned cnt  = (unsigned)s1 - off;
    unsigned base = (unsigned)(s0 >> 32);           // coffs[v]
    unsigned c = min(cnt, (unsigned)KCAP);

    // grid row + vox_count (every voxel)
    float vals[KCAP];
#pragma unroll
    for (int s = 0; s < KCAP; s++)
        vals[s] = (s < (int)c) ? (float)(base + (unsigned)s) : -1.0f;
    float4* gp = (float4*)(out + OFF_GRID + (size_t)v * KCAP);
#pragma unroll
    for (int q = 0; q < 4; q++)
        gp[q] = make_float4(vals[4 * q], vals[4 * q + 1], vals[4 * q + 2],
                            vals[4 * q + 3]);
    out[OFF_VC + v] = (float)c;

    if (c == 0) return;

    // register-resident ascending top-16 (keys unique -> total order)
    unsigned long long best[KCAP];
#pragma unroll
    for (int s = 0; s < KCAP; s++) best[s] = ~0ull;
    for (unsigned j = 0; j < cnt; j++) {
        unsigned long long cur = g_bins[off + j];
        if (cur < best[KCAP - 1]) {
#pragma unroll
            for (int t = 0; t < KCAP; t++) {
                unsigned long long lo = min(best[t], cur);
                cur = max(best[t], cur);
                best[t] = lo;
            }
        }
    }
    for (unsigned s = 0; s < c; s++)
        g_pid[base + s] = (unsigned)best[s];        // low 32 = original idx
}

// output-driven gather: 4 rows/thread; random reads are 4 sectors/row
// (1 record + 3 desc); all writes coalesced; tail zeroed inline.
__global__ void k_out(const float* __restrict__ desc,
                      const float* __restrict__ dmean,
                      const float* __restrict__ dstd,
                      float* __restrict__ out) {
    int r0 = 4 * (blockIdx.x * blockDim.x + threadIdx.x);
    if (r0 >= NPTS) return;
    unsigned M = (unsigned)(g_scan64[NUM_VOX] >> 32);   // total survivors

    const float4* m4 = (const float4*)dmean;
    const float4* s4 = (const float4*)dstd;

    if ((unsigned)(r0 + 3) < M) {
        uint4 p4 = *(const uint4*)(g_pid + r0);
        unsigned pid[4] = {p4.x, p4.y, p4.z, p4.w};

        float4 ra[4], rb[4];
#pragma unroll
        for (int k = 0; k < 4; k++) {
            ra[k] = g_rec[2 * (size_t)pid[k]];
            rb[k] = g_rec[2 * (size_t)pid[k] + 1];
        }
        float4* pp = (float4*)(out + OFF_PTS + 3 * (size_t)r0);
        pp[0] = make_float4(ra[0].x, ra[0].y, ra[0].z, ra[1].x);
        pp[1] = make_float4(ra[1].y, ra[1].z, ra[2].x, ra[2].y);
        pp[2] = make_float4(ra[2].z, ra[3].x, ra[3].y, ra[3].z);
        *(float4*)(out + OFF_CONF + r0) =
            make_float4(ra[0].w, ra[1].w, ra[2].w, ra[3].w);
        *(float4*)(out + OFF_DC + r0) =
            make_float4(rb[0].x, rb[1].x, rb[2].x, rb[3].x);

#pragma unroll
        for (int k = 0; k < 4; k++) {
            unsigned p = pid[k];
            const float4* dsrc = (const float4*)(desc + (size_t)DDESC * p);
            float4* ddst = (float4*)(out + OFF_DESC + (size_t)DDESC * (r0 + k));
#pragma unroll
            for (int q = 0; q < 6; q++) {
                float4 d = dsrc[q];
                float4 m = m4[q];
                float4 s2 = s4[q];
                float4 w;
                w.x = __fdiv_rn(d.x - m.x, s2.x);
                w.y = __fdiv_rn(d.y - m.y, s2.y);
                w.z = __fdiv_rn(d.z - m.z, s2.z);
                w.w = __fdiv_rn(d.w - m.w, s2.w);
                ddst[q] = w;
            }
        }
    } else {
        // boundary / tail: per-row scalar
#pragma unroll
        for (int k = 0; k < 4; k++) {
            int r = r0 + k;
            if (r >= NPTS) break;
            if ((unsigned)r < M) {
                unsigned p = g_pid[r];
                float4 ra = g_rec[2 * (size_t)p];
                float4 rb = g_rec[2 * (size_t)p + 1];
                out[OFF_PTS + 3 * (size_t)r + 0] = ra.x;
                out[OFF_PTS + 3 * (size_t)r + 1] = ra.y;
                out[OFF_PTS + 3 * (size_t)r + 2] = ra.z;
                out[OFF_CONF + r] = ra.w;
                out[OFF_DC + r] = rb.x;
                const float4* dsrc = (const float4*)(desc + (size_t)DDESC * p);
                float4* ddst = (float4*)(out + OFF_DESC + (size_t)DDESC * r);
#pragma unroll
                for (int q = 0; q < 6; q++) {
                    float4 d = dsrc[q];
                    float4 m = m4[q];
                    float4 s2 = s4[q];
                    float4 w;
                    w.x = __fdiv_rn(d.x - m.x, s2.x);
                    w.y = __fdiv_rn(d.y - m.y, s2.y);
                    w.z = __fdiv_rn(d.z - m.z, s2.z);
                    w.w = __fdiv_rn(d.w - m.w, s2.w);
                    ddst[q] = w;
                }
            } else {
                out[OFF_PTS + 3 * (size_t)r + 0] = 0.0f;
                out[OFF_PTS + 3 * (size_t)r + 1] = 0.0f;
                out[OFF_PTS + 3 * (size_t)r + 2] = 0.0f;
                out[OFF_CONF + r] = 0.0f;
                out[OFF_DC + r] = 0.0f;
                float4 z = make_float4(0.f, 0.f, 0.f, 0.f);
                float4* dz = (float4*)(out + OFF_DESC + (size_t)DDESC * r);
#pragma unroll
                for (int q = 0; q < 6; q++) dz[q] = z;
            }
        }
    }
}

// ---------------- launch ----------------
extern "C" void kernel_launch(void* const* d_in, const int* in_sizes, int n_in,
                              void* d_out, int out_size) {
    const float* pts    = (const float*)d_in[0];
    const float* conf   = (const float*)d_in[1];
    const float* desc   = (const float*)d_in[2];
    const float* dconf  = (const float*)d_in[3];
    const float* dmean  = (const float*)d_in[4];
    const float* dstd   = (const float*)d_in[5];
    const float* dcm    = (const float*)d_in[6];
    const float* dcs    = (const float*)d_in[7];
    const float* center = (const float*)d_in[8];
    float* out = (float*)d_out;

    void *pSconf, *pCnt, *pCv, *pCo, *pTmp, *pTmp2;
    cudaGetSymbolAddress(&pSconf, g_sconf);
    cudaGetSymbolAddress(&pCnt,   g_counts);
    cudaGetSymbolAddress(&pCv,    g_cvals64);
    cudaGetSymbolAddress(&pCo,    g_scan64);
    cudaGetSymbolAddress(&pTmp,   g_temp);
    cudaGetSymbolAddress(&pTmp2,  g_temp2);
    const size_t TEMP_CAP  = (size_t)64 * 1024 * 1024;
    const size_t TEMP2_CAP = (size_t)16 * 1024 * 1024;

    const int T = 256;
    const int GN = (NPTS + T - 1) / T;
    const int GV = (NUM_VOX + T - 1) / T;
    const int GV1 = (NUM_VOX + 1 + T - 1) / T;
    const int GO = (NPTS / 4 + T - 1) / T;

    cudaMemsetAsync(pCnt, 0, (size_t)(NUM_VOX + 1) * sizeof(unsigned));

    // conf values sort (keys only; bits order == value order for conf >= 0)
    size_t tb = 0;
    cub::DeviceRadixSort::SortKeys(nullptr, tb,
        (const unsigned*)conf, (unsigned*)pSconf, NPTS, 0, 32);
    if (tb <= TEMP_CAP)
        cub::DeviceRadixSort::SortKeys(pTmp, tb,
            (const unsigned*)conf, (unsigned*)pSconf, NPTS, 0, 32);

    k_prep<<<GN, T>>>(pts, center);
    k_capped<<<GV1, T>>>();

    // fused dual exclusive scan: low32 = offsets (scan of counts),
    // high32 = coffs (scan of min(counts,16)); no cross-field carry possible.
    size_t sb = 0;
    cub::DeviceScan::ExclusiveSum(nullptr, sb,
        (const unsigned long long*)pCv, (unsigned long long*)pCo, NUM_VOX + 1);
    if (sb <= TEMP2_CAP)
        cub::DeviceScan::ExclusiveSum(pTmp2, sb,
            (const unsigned long long*)pCv, (unsigned long long*)pCo,
            NUM_VOX + 1);

    k_bin<<<GN, T>>>(pts, conf, dconf, dcm, dcs);
    k_rank_grid<<<GV, T>>>(out);
    k_out<<<GO, T>>>(desc, dmean, dstd, out);
}

// round 11
// speedup vs baseline: 1.0079x; 1.0079x over previous
#include <cuda_runtime.h>
#include <cub/cub.cuh>
#include <cstdint>

// ---------------- problem constants ----------------
#define NPTS     3145728
#define GDIM     128
#define NUM_VOX  2097152   // GDIM^3
#define KCAP     16
#define DDESC    24

// output layout (floats), tuple order of the reference
#define OFF_PTS   ((size_t)0)
#define OFF_CONF  ((size_t)3 * NPTS)
#define OFF_DESC  ((size_t)4 * NPTS)
#define OFF_DC    ((size_t)28 * NPTS)
#define OFF_GRID  ((size_t)29 * NPTS)
#define OFF_VC    (OFF_GRID + (size_t)NUM_VOX * KCAP)

// ---------------- device scratch (static: no allocation allowed) ----------------
__device__ unsigned g_sconf[NPTS];                    // conf bits, ascending-sorted
__device__ unsigned g_vid[NPTS];
__device__ unsigned g_pid[NPTS];                      // compact slot -> point id
__device__ float4   g_rec[(size_t)2 * NPTS];          // 32B/point: {x,y,z,conf},{dc,-,-,-}
__device__ unsigned long long g_bins[NPTS];           // per-voxel (~conf,idx) keys
__device__ unsigned g_counts[NUM_VOX + 1];
__device__ unsigned long long g_cvals64[NUM_VOX + 1]; // (capped<<32)|count
__device__ unsigned long long g_scan64[NUM_VOX + 1];  // (coffs <<32)|offsets
__device__ unsigned char g_temp[(size_t)64 * 1024 * 1024];   // sort temp
__device__ unsigned char g_temp2[(size_t)16 * 1024 * 1024];  // scan temp

// ---------------- kernels ----------------

// voxel id + histogram
__global__ void k_prep(const float* __restrict__ pts,
                       const float* __restrict__ center) {
    int i = blockIdx.x * blockDim.x + threadIdx.x;
    if (i >= NPTS) return;

    const float HALF = (float)((256.0 * 0.02) / 2.0);   // CUBE/2
    // XLA rewrites divide-by-constant into multiply by reciprocal;
    // f32(1 / f32(0.04)) rounds to exactly 25.0f.
    const float INV_MRES = 25.0f;

    float mx = center[0] - HALF;
    float my = center[1] - HALF;
    float mz = center[2] - HALF;

    float px = pts[3 * (size_t)i + 0];
    float py = pts[3 * (size_t)i + 1];
    float pz = pts[3 * (size_t)i + 2];

    int ix = (int)((px - mx) * INV_MRES);
    int iy = (int)((py - my) * INV_MRES);
    int iz = (int)((pz - mz) * INV_MRES);

    bool inb = (ix >= 0) && (ix < GDIM) && (iy >= 0) && (iy < GDIM) &&
               (iz >= 0) && (iz < GDIM);
    unsigned v = inb ? (unsigned)(ix * GDIM * GDIM + iy * GDIM + iz)
                     : (unsigned)NUM_VOX;
    g_vid[i] = v;
    atomicAdd(&g_counts[v], 1u);
}

// packed counts for the fused dual scan
__global__ void k_capped() {
    int v = blockIdx.x * blockDim.x + threadIdx.x;
    if (v > NUM_VOX) return;
    unsigned c = g_counts[v];
    unsigned capped = (v < NUM_VOX) ? min(c, (unsigned)KCAP) : 0u;
    g_cvals64[v] = ((unsigned long long)capped << 32) | (unsigned long long)c;
}

// binning + staging-record build. All reads coalesced; unique bin slots via
// atomicSub on the (now dead) counts array.
__global__ void k_bin(const float* __restrict__ pts,
                      const float* __restrict__ conf,
                      const float* __restrict__ dconf,
                      const float* __restrict__ dcm,
                      const float* __restrict__ dcs) {
    int i = blockIdx.x * blockDim.x + threadIdx.x;
    if (i >= NPTS) return;

    // staging record: 1 random 32B sector in k_out replaces 4 random sectors
    float4 r0;
    r0.x = pts[3 * (size_t)i + 0];
    r0.y = pts[3 * (size_t)i + 1];
    r0.z = pts[3 * (size_t)i + 2];
    // faithful quirk value: conf_sorted(desc)[p] == asc-sorted[N-1-p]
    r0.w = __uint_as_float(g_sconf[NPTS - 1 - i]);
    float dc = __fdiv_rn(dconf[i] - dcm[0], dcs[0]);
    g_rec[2 * (size_t)i]     = r0;
    g_rec[2 * (size_t)i + 1] = make_float4(dc, 0.f, 0.f, 0.f);

    unsigned v = g_vid[i];
    if (v >= NUM_VOX) return;
    unsigned slot = atomicSub(&g_counts[v], 1u) - 1u;
    unsigned off = (unsigned)g_scan64[v];           // offsets[v]
    unsigned long long key =
        ((unsigned long long)(~__float_as_uint(conf[i])) << 32) |
        (unsigned long long)(unsigned)i;
    g_bins[off + slot] = key;
}

// per-voxel top-16 selection -> compact pid list + analytic grid/vox_counts
__global__ void k_rank_grid(float* __restrict__ out) {
    int v = blockIdx.x * blockDim.x + threadIdx.x;
    if (v >= NUM_VOX) return;
    unsigned long long s0 = g_scan64[v];
    unsigned long long s1 = g_scan64[v + 1];
    unsigned off  = (unsigned)s0;
    unsigned cnt  = (unsigned)s1 - off;
    unsigned base = (unsigned)(s0 >> 32);           // coffs[v]
    unsigned c = min(cnt, (unsigned)KCAP);

    // grid row + vox_count (every voxel)
    float vals[KCAP];
#pragma unroll
    for (int s = 0; s < KCAP; s++)
        vals[s] = (s < (int)c) ? (float)(base + (unsigned)s) : -1.0f;
    float4* gp = (float4*)(out + OFF_GRID + (size_t)v * KCAP);
#pragma unroll
    for (int q = 0; q < 4; q++)
        gp[q] = make_float4(vals[4 * q], vals[4 * q + 1], vals[4 * q + 2],
                            vals[4 * q + 3]);
    out[OFF_VC + v] = (float)c;

    if (c == 0) return;

    // register-resident ascending top-16 (keys unique -> total order)
    unsigned long long best[KCAP];
#pragma unroll
    for (int s = 0; s < KCAP; s++) best[s] = ~0ull;
    for (unsigned j = 0; j < cnt; j++) {
        unsigned long long cur = g_bins[off + j];
        if (cur < best[KCAP - 1]) {
#pragma unroll
            for (int t = 0; t < KCAP; t++) {
                unsigned long long lo = min(best[t], cur);
                cur = max(best[t], cur);
                best[t] = lo;
            }
        }
    }
    for (unsigned s = 0; s < c; s++)
        g_pid[base + s] = (unsigned)best[s];        // low 32 = original idx
}

// output-driven gather: 4 rows/thread; random reads are 4 sectors/row
// (1 record + 3 desc); all writes coalesced; tail zeroed inline.
__global__ void k_out(const float* __restrict__ desc,
                      const float* __restrict__ dmean,
                      const float* __restrict__ dstd,
                      float* __restrict__ out) {
    int r0 = 4 * (blockIdx.x * blockDim.x + threadIdx.x);
    if (r0 >= NPTS) return;
    unsigned M = (unsigned)(g_scan64[NUM_VOX] >> 32);   // total survivors

    const float4* m4 = (const float4*)dmean;
    const float4* s4 = (const float4*)dstd;

    if ((unsigned)(r0 + 3) < M) {
        uint4 p4 = *(const uint4*)(g_pid + r0);
        unsigned pid[4] = {p4.x, p4.y, p4.z, p4.w};

        float4 ra[4], rb[4];
#pragma unroll
        for (int k = 0; k < 4; k++) {
            ra[k] = g_rec[2 * (size_t)pid[k]];
            rb[k] = g_rec[2 * (size_t)pid[k] + 1];
        }
        float4* pp = (float4*)(out + OFF_PTS + 3 * (size_t)r0);
        pp[0] = make_float4(ra[0].x, ra[0].y, ra[0].z, ra[1].x);
        pp[1] = make_float4(ra[1].y, ra[1].z, ra[2].x, ra[2].y);
        pp[2] = make_float4(ra[2].z, ra[3].x, ra[3].y, ra[3].z);
        *(float4*)(out + OFF_CONF + r0) =
            make_float4(ra[0].w, ra[1].w, ra[2].w, ra[3].w);
        *(float4*)(out + OFF_DC + r0) =
            make_float4(rb[0].x, rb[1].x, rb[2].x, rb[3].x);

#pragma unroll
        for (int k = 0; k < 4; k++) {
            unsigned p = pid[k];
            const float4* dsrc = (const float4*)(desc + (size_t)DDESC * p);
            float4* ddst = (float4*)(out + OFF_DESC + (size_t)DDESC * (r0 + k));
#pragma unroll
            for (int q = 0; q < 6; q++) {
                float4 d = dsrc[q];
                float4 m = m4[q];
                float4 s2 = s4[q];
                float4 w;
                w.x = __fdiv_rn(d.x - m.x, s2.x);
                w.y = __fdiv_rn(d.y - m.y, s2.y);
                w.z = __fdiv_rn(d.z - m.z, s2.z);
                w.w = __fdiv_rn(d.w - m.w, s2.w);
                ddst[q] = w;
            }
        }
    } else {
        // boundary / tail: per-row scalar
#pragma unroll
        for (int k = 0; k < 4; k++) {
            int r = r0 + k;
            if (r >= NPTS) break;
            if ((unsigned)r < M) {
                unsigned p = g_pid[r];
                float4 ra = g_rec[2 * (size_t)p];
                float4 rb = g_rec[2 * (size_t)p + 1];
                out[OFF_PTS + 3 * (size_t)r + 0] = ra.x;
                out[OFF_PTS + 3 * (size_t)r + 1] = ra.y;
                out[OFF_PTS + 3 * (size_t)r + 2] = ra.z;
                out[OFF_CONF + r] = ra.w;
                out[OFF_DC + r] = rb.x;
                const float4* dsrc = (const float4*)(desc + (size_t)DDESC * p);
                float4* ddst = (float4*)(out + OFF_DESC + (size_t)DDESC * r);
#pragma unroll
                for (int q = 0; q < 6; q++) {
                    float4 d = dsrc[q];
                    float4 m = m4[q];
                    float4 s2 = s4[q];
                    float4 w;
                    w.x = __fdiv_rn(d.x - m.x, s2.x);
                    w.y = __fdiv_rn(d.y - m.y, s2.y);
                    w.z = __fdiv_rn(d.z - m.z, s2.z);
                    w.w = __fdiv_rn(d.w - m.w, s2.w);
                    ddst[q] = w;
                }
            } else {
                out[OFF_PTS + 3 * (size_t)r + 0] = 0.0f;
                out[OFF_PTS + 3 * (size_t)r + 1] = 0.0f;
                out[OFF_PTS + 3 * (size_t)r + 2] = 0.0f;
                out[OFF_CONF + r] = 0.0f;
                out[OFF_DC + r] = 0.0f;
                float4 z = make_float4(0.f, 0.f, 0.f, 0.f);
                float4* dz = (float4*)(out + OFF_DESC + (size_t)DDESC * r);
#pragma unroll
                for (int q = 0; q < 6; q++) dz[q] = z;
            }
        }
    }
}

// ---------------- launch ----------------
extern "C" void kernel_launch(void* const* d_in, const int* in_sizes, int n_in,
                              void* d_out, int out_size) {
    const float* pts    = (const float*)d_in[0];
    const float* conf   = (const float*)d_in[1];
    const float* desc   = (const float*)d_in[2];
    const float* dconf  = (const float*)d_in[3];
    const float* dmean  = (const float*)d_in[4];
    const float* dstd   = (const float*)d_in[5];
    const float* dcm    = (const float*)d_in[6];
    const float* dcs    = (const float*)d_in[7];
    const float* center = (const float*)d_in[8];
    float* out = (float*)d_out;

    void *pSconf, *pCnt, *pCv, *pCo, *pTmp, *pTmp2;
    cudaGetSymbolAddress(&pSconf, g_sconf);
    cudaGetSymbolAddress(&pCnt,   g_counts);
    cudaGetSymbolAddress(&pCv,    g_cvals64);
    cudaGetSymbolAddress(&pCo,    g_scan64);
    cudaGetSymbolAddress(&pTmp,   g_temp);
    cudaGetSymbolAddress(&pTmp2,  g_temp2);
    const size_t TEMP_CAP  = (size_t)64 * 1024 * 1024;
    const size_t TEMP2_CAP = (size_t)16 * 1024 * 1024;

    const int T = 256;
    const int GN = (NPTS + T - 1) / T;
    const int GV = (NUM_VOX + T - 1) / T;
    const int GV1 = (NUM_VOX + 1 + T - 1) / T;
    const int GO = (NPTS / 4 + T - 1) / T;

    cudaMemsetAsync(pCnt, 0, (size_t)(NUM_VOX + 1) * sizeof(unsigned));

    // conf values sort (keys only; bits order == value order for conf >= 0)
    size_t tb = 0;
    cub::DeviceRadixSort::SortKeys(nullptr, tb,
        (const unsigned*)conf, (unsigned*)pSconf, NPTS, 0, 32);
    if (tb <= TEMP_CAP)
        cub::DeviceRadixSort::SortKeys(pTmp, tb,
            (const unsigned*)conf, (unsigned*)pSconf, NPTS, 0, 32);

    k_prep<<<GN, T>>>(pts, center);
    k_capped<<<GV1, T>>>();

    // fused dual exclusive scan: low32 = offsets (scan of counts),
    // high32 = coffs (scan of min(counts,16)); no cross-field carry possible.
    size_t sb = 0;
    cub::DeviceScan::ExclusiveSum(nullptr, sb,
        (const unsigned long long*)pCv, (unsigned long long*)pCo, NUM_VOX + 1);
    if (sb <= TEMP2_CAP)
        cub::DeviceScan::ExclusiveSum(pTmp2, sb,
            (const unsigned long long*)pCv, (unsigned long long*)pCo,
            NUM_VOX + 1);

    k_bin<<<GN, T>>>(pts, conf, dconf, dcm, dcs);
    k_rank_grid<<<GV, T>>>(out);
    k_out<<<GO, T>>>(desc, dmean, dstd, out);
}

// round 12
// speedup vs baseline: 1.9923x; 1.9767x over previous
#include <cuda_runtime.h>
#include <cub/cub.cuh>
#include <cstdint>

// ---------------- problem constants ----------------
#define NPTS     3145728
#define GDIM     128
#define NUM_VOX  2097152   // GDIM^3
#define KCAP     16
#define DDESC    24

// output layout (floats), tuple order of the reference
#define OFF_PTS   ((size_t)0)
#define OFF_CONF  ((size_t)3 * NPTS)
#define OFF_DESC  ((size_t)4 * NPTS)
#define OFF_DC    ((size_t)28 * NPTS)
#define OFF_GRID  ((size_t)29 * NPTS)
#define OFF_VC    (OFF_GRID + (size_t)NUM_VOX * KCAP)

// ---------------- device scratch (static: no allocation allowed) ----------------
__device__ unsigned g_sconf[NPTS];                    // conf bits, ascending-sorted
__device__ unsigned g_vid[NPTS];
__device__ unsigned g_pid[NPTS];                      // compact slot -> point id
__device__ unsigned long long g_bins[NPTS];           // per-voxel (~conf,idx) keys
__device__ unsigned g_counts[NUM_VOX + 1];            // zero at entry; self-cleaning
__device__ unsigned long long g_cvals64[NUM_VOX + 1]; // (capped<<32)|count
__device__ unsigned long long g_scan64[NUM_VOX + 1];  // (coffs <<32)|offsets
__device__ unsigned char g_temp[(size_t)64 * 1024 * 1024];   // sort temp
__device__ unsigned char g_temp2[(size_t)16 * 1024 * 1024];  // scan temp

// ---------------- kernels ----------------

// voxel id + histogram. Only in-bounds points touch g_counts, and k_bin's
// atomicSub drains each counter back to 0 -> no memset needed between runs.
__global__ void k_prep(const float* __restrict__ pts,
                       const float* __restrict__ center) {
    int i = blockIdx.x * blockDim.x + threadIdx.x;
    if (i >= NPTS) return;

    const float HALF = (float)((256.0 * 0.02) / 2.0);   // CUBE/2
    // XLA rewrites divide-by-constant into multiply by reciprocal;
    // f32(1 / f32(0.04)) rounds to exactly 25.0f.
    const float INV_MRES = 25.0f;

    float mx = center[0] - HALF;
    float my = center[1] - HALF;
    float mz = center[2] - HALF;

    float px = pts[3 * (size_t)i + 0];
    float py = pts[3 * (size_t)i + 1];
    float pz = pts[3 * (size_t)i + 2];

    int ix = (int)((px - mx) * INV_MRES);
    int iy = (int)((py - my) * INV_MRES);
    int iz = (int)((pz - mz) * INV_MRES);

    bool inb = (ix >= 0) && (ix < GDIM) && (iy >= 0) && (iy < GDIM) &&
               (iz >= 0) && (iz < GDIM);
    unsigned v = inb ? (unsigned)(ix * GDIM * GDIM + iy * GDIM + iz)
                     : (unsigned)NUM_VOX;
    g_vid[i] = v;
    if (inb) atomicAdd(&g_counts[v], 1u);
}

// packed counts for the fused dual scan
__global__ void k_capped() {
    int v = blockIdx.x * blockDim.x + threadIdx.x;
    if (v > NUM_VOX) return;
    unsigned c = g_counts[v];
    unsigned capped = (v < NUM_VOX) ? min(c, (unsigned)KCAP) : 0u;
    g_cvals64[v] = ((unsigned long long)capped << 32) | (unsigned long long)c;
}

// counting-sort binning; unique slots via atomicSub (drains counts to zero).
__global__ void k_bin(const float* __restrict__ conf) {
    int i = blockIdx.x * blockDim.x + threadIdx.x;
    if (i >= NPTS) return;
    unsigned v = g_vid[i];
    if (v >= NUM_VOX) return;
    unsigned slot = atomicSub(&g_counts[v], 1u) - 1u;
    unsigned off = (unsigned)g_scan64[v];           // offsets[v]
    unsigned long long key =
        ((unsigned long long)(~__float_as_uint(conf[i])) << 32) |
        (unsigned long long)(unsigned)i;
    g_bins[off + slot] = key;
}

// per-voxel top-16 selection -> compact pid list + analytic grid/vox_counts
__global__ void k_rank_grid(float* __restrict__ out) {
    int v = blockIdx.x * blockDim.x + threadIdx.x;
    if (v >= NUM_VOX) return;
    unsigned long long s0 = g_scan64[v];
    unsigned long long s1 = g_scan64[v + 1];
    unsigned off  = (unsigned)s0;
    unsigned cnt  = (unsigned)s1 - off;
    unsigned base = (unsigned)(s0 >> 32);           // coffs[v]
    unsigned c = min(cnt, (unsigned)KCAP);

    // grid row + vox_count (every voxel)
    float vals[KCAP];
#pragma unroll
    for (int s = 0; s < KCAP; s++)
        vals[s] = (s < (int)c) ? (float)(base + (unsigned)s) : -1.0f;
    float4* gp = (float4*)(out + OFF_GRID + (size_t)v * KCAP);
#pragma unroll
    for (int q = 0; q < 4; q++)
        gp[q] = make_float4(vals[4 * q], vals[4 * q + 1], vals[4 * q + 2],
                            vals[4 * q + 3]);
    out[OFF_VC + v] = (float)c;

    if (c == 0) return;

    // register-resident ascending top-16 (keys unique -> total order)
    unsigned long long best[KCAP];
#pragma unroll
    for (int s = 0; s < KCAP; s++) best[s] = ~0ull;
    for (unsigned j = 0; j < cnt; j++) {
        unsigned long long cur = g_bins[off + j];
        if (cur < best[KCAP - 1]) {
#pragma unroll
            for (int t = 0; t < KCAP; t++) {
                unsigned long long lo = min(best[t], cur);
                cur = max(best[t], cur);
                best[t] = lo;
            }
        }
    }
    for (unsigned s = 0; s < c; s++)
        g_pid[base + s] = (unsigned)best[s];        // low 32 = original idx
}

// warp-cooperative output gather: each warp owns 32 output rows.
// desc rows fetched warp-wide (one coalesced 96B request per row, 32
// independent requests in flight per warp), all stores coalesced, tail zeroed.
__global__ void k_out(const float* __restrict__ pts,
                      const float* __restrict__ desc,
                      const float* __restrict__ dconf,
                      const float* __restrict__ dmean,
                      const float* __restrict__ dstd,
                      const float* __restrict__ dcm,
                      const float* __restrict__ dcs,
                      float* __restrict__ out) {
    int warp_id = (blockIdx.x * blockDim.x + threadIdx.x) >> 5;
    int lane = threadIdx.x & 31;
    int r0 = warp_id << 5;
    if (r0 >= NPTS) return;                          // warp-uniform
    unsigned M = (unsigned)(g_scan64[NUM_VOX] >> 32);   // total survivors

    // scalar fields: one row per lane
    int r = r0 + lane;                               // r < NPTS (NPTS % 32 == 0)
    bool live = (unsigned)r < M;
    unsigned p = live ? g_pid[r] : 0u;

    float x = 0.f, y = 0.f, z = 0.f, cv = 0.f, dc = 0.f;
    if (live) {
        x = pts[3 * (size_t)p + 0];
        y = pts[3 * (size_t)p + 1];
        z = pts[3 * (size_t)p + 2];
        // faithful quirk: conf_sorted(desc)[p] == asc-sorted[N-1-p]
        cv = __uint_as_float(g_sconf[NPTS - 1 - (int)p]);
        dc = __fdiv_rn(dconf[p] - dcm[0], dcs[0]);
    }
    out[OFF_PTS + 3 * (size_t)r + 0] = x;
    out[OFF_PTS + 3 * (size_t)r + 1] = y;
    out[OFF_PTS + 3 * (size_t)r + 2] = z;
    out[OFF_CONF + r] = cv;
    out[OFF_DC + r] = dc;

    // desc: lanes 0..23 cover one 24-float row per iteration
    float mv = (lane < DDESC) ? dmean[lane] : 0.f;
    float sv = (lane < DDESC) ? dstd[lane] : 1.f;
#pragma unroll 8
    for (int k = 0; k < 32; k++) {
        unsigned pk = __shfl_sync(0xffffffffu, p, k);
        int rr = r0 + k;
        float w = 0.f;
        if ((unsigned)rr < M && lane < DDESC)
            w = __fdiv_rn(desc[(size_t)pk * DDESC + lane] - mv, sv);
        if (lane < DDESC)
            out[OFF_DESC + (size_t)rr * DDESC + lane] = w;
    }
}

// ---------------- launch ----------------
extern "C" void kernel_launch(void* const* d_in, const int* in_sizes, int n_in,
                              void* d_out, int out_size) {
    const float* pts    = (const float*)d_in[0];
    const float* conf   = (const float*)d_in[1];
    const float* desc   = (const float*)d_in[2];
    const float* dconf  = (const float*)d_in[3];
    const float* dmean  = (const float*)d_in[4];
    const float* dstd   = (const float*)d_in[5];
    const float* dcm    = (const float*)d_in[6];
    const float* dcs    = (const float*)d_in[7];
    const float* center = (const float*)d_in[8];
    float* out = (float*)d_out;

    void *pSconf, *pCv, *pCo, *pTmp, *pTmp2;
    cudaGetSymbolAddress(&pSconf, g_sconf);
    cudaGetSymbolAddress(&pCv,    g_cvals64);
    cudaGetSymbolAddress(&pCo,    g_scan64);
    cudaGetSymbolAddress(&pTmp,   g_temp);
    cudaGetSymbolAddress(&pTmp2,  g_temp2);
    const size_t TEMP_CAP  = (size_t)64 * 1024 * 1024;
    const size_t TEMP2_CAP = (size_t)16 * 1024 * 1024;

    const int T = 256;
    const int GN = (NPTS + T - 1) / T;
    const int GV = (NUM_VOX + T - 1) / T;
    const int GV1 = (NUM_VOX + 1 + T - 1) / T;
    const int GW = (NPTS / 32 * 32 + T - 1) / T;   // warp-per-32-rows grid

    // conf values sort (keys only; bits order == value order for conf >= 0)
    size_t tb = 0;
    cub::DeviceRadixSort::SortKeys(nullptr, tb,
        (const unsigned*)conf, (unsigned*)pSconf, NPTS, 0, 32);
    if (tb <= TEMP_CAP)
        cub::DeviceRadixSort::SortKeys(pTmp, tb,
            (const unsigned*)conf, (unsigned*)pSconf, NPTS, 0, 32);

    k_prep<<<GN, T>>>(pts, center);
    k_capped<<<GV1, T>>>();

    // fused dual exclusive scan: low32 = offsets (scan of counts),
    // high32 = coffs (scan of min(counts,16)); no cross-field carry possible.
    size_t sb = 0;
    cub::DeviceScan::ExclusiveSum(nullptr, sb,
        (const unsigned long long*)pCv, (unsigned long long*)pCo, NUM_VOX + 1);
    if (sb <= TEMP2_CAP)
        cub::DeviceScan::ExclusiveSum(pTmp2, sb,
            (const unsigned long long*)pCv, (unsigned long long*)pCo,
            NUM_VOX + 1);

    k_bin<<<GN, T>>>(conf);
    k_rank_grid<<<GV, T>>>(out);
    k_out<<<GW, T>>>(pts, desc, dconf, dmean, dstd, dcm, dcs, out);
}